// round 1
// baseline (speedup 1.0000x reference)
#include <cuda_runtime.h>

// Problem constants
#define GAMMA 0.1f
#define TAU   0.01f
#define NN    256          // neuron count
#define MM    512          // astrocyte count
#define KK    512          // input dim
#define NN2   (NN * NN)    // 65536
#define SPLIT 16           // chunks per H row
#define CHUNK (NN2 / SPLIT) // 4096 floats per chunk

// Scratch (no allocations allowed in kernel_launch)
__device__ float g_phi[NN];           // sigmoid(x_new)
__device__ float g_part[MM * SPLIT];  // H@Phi partial sums

__device__ __forceinline__ float warp_sum(float v) {
#pragma unroll
    for (int o = 16; o > 0; o >>= 1) v += __shfl_xor_sync(0xffffffffu, v, o);
    return v;
}

__device__ __forceinline__ float sigmoidf(float v) {
    return 1.0f / (1.0f + expf(-v));
}

// ---------------------------------------------------------------------------
// Kernel A: x_new = (1-g)x + g*(W @ sigmoid(x)) + W_in_1 @ I ; g_phi = sigmoid(x_new)
// 32 blocks x 256 threads, warp-per-row (256 rows).
// ---------------------------------------------------------------------------
__global__ void kA(const float* __restrict__ x, const float* __restrict__ W,
                   const float* __restrict__ Win1, const float* __restrict__ I,
                   float* __restrict__ out_x) {
    __shared__ float s_phi[NN];
    __shared__ float s_I[KK];
    int tid = threadIdx.x;  // 256
    s_phi[tid]      = sigmoidf(x[tid]);
    s_I[tid]        = I[tid];
    s_I[tid + 256]  = I[tid + 256];
    __syncthreads();

    int warp = tid >> 5, lane = tid & 31;
    int row = blockIdx.x * 8 + warp;

    float a1 = 0.0f, a2 = 0.0f;
    const float* wr = W + (size_t)row * NN;
#pragma unroll
    for (int j = lane; j < NN; j += 32) a1 += wr[j] * s_phi[j];
    const float* w1 = Win1 + (size_t)row * KK;
#pragma unroll
    for (int k = lane; k < KK; k += 32) a2 += w1[k] * s_I[k];

    a1 = warp_sum(a1);
    a2 = warp_sum(a2);
    if (lane == 0) {
        float xn = (1.0f - GAMMA) * x[row] + GAMMA * a1 + a2;
        out_x[row] = xn;
        g_phi[row] = sigmoidf(xn);
    }
}

// ---------------------------------------------------------------------------
// Kernel C: W_new[p] = (1-g)*W[p] + g*( C[p]*phi[i]*phi[j] + (D @ tanh(z))[p] )
// Warp-per-output-row. 8192 blocks x 256 threads. Each block reads 16 KB of D
// contiguously via float4.
// ---------------------------------------------------------------------------
__global__ void kC(const float* __restrict__ W, const float* __restrict__ C,
                   const float* __restrict__ D, const float* __restrict__ z,
                   float* __restrict__ out_W) {
    __shared__ float s_psi[MM];
    int tid = threadIdx.x;  // 256
    s_psi[tid]       = tanhf(z[tid]);
    s_psi[tid + 256] = tanhf(z[tid + 256]);
    __syncthreads();

    int warp = tid >> 5, lane = tid & 31;
    int p = blockIdx.x * 8 + warp;

    const float4* dr = (const float4*)(D + (size_t)p * MM);
    const float4* ps = (const float4*)s_psi;
    float acc = 0.0f;
#pragma unroll
    for (int q = 0; q < 4; q++) {
        int idx = lane + 32 * q;       // 128 float4 per 512-float row
        float4 d = dr[idx];
        float4 s = ps[idx];
        acc += d.x * s.x + d.y * s.y + d.z * s.z + d.w * s.w;
    }
    acc = warp_sum(acc);
    if (lane == 0) {
        int i = p >> 8, j = p & 255;
        float ph = g_phi[i] * g_phi[j];
        out_W[p] = (1.0f - GAMMA) * W[p] + GAMMA * (C[p] * ph + acc);
    }
}

// ---------------------------------------------------------------------------
// Kernel D1: partial sums of H @ Phi, where Phi[p] = phi[p>>8]*phi[p&255].
// grid = (SPLIT, MM); block = 256 threads; each block reduces a 16 KB chunk
// of one H row into g_part[m*SPLIT + c].
// ---------------------------------------------------------------------------
__global__ void kD1(const float* __restrict__ H) {
    __shared__ float s_phi[NN];
    __shared__ float s_red[8];
    int tid = threadIdx.x;  // 256
    s_phi[tid] = g_phi[tid];
    __syncthreads();

    int c = blockIdx.x;  // chunk
    int m = blockIdx.y;  // row
    const float4* hr = (const float4*)(H + (size_t)m * NN2 + (size_t)c * CHUNK);

    float acc = 0.0f;
#pragma unroll
    for (int q = 0; q < 4; q++) {
        int f = tid + 256 * q;        // float4 index within chunk (0..1023)
        int p = c * CHUNK + f * 4;    // element index within row (i const per float4)
        float4 h = hr[f];
        int i = p >> 8;
        int j = p & 255;              // multiple of 4, so j+3 <= 255
        float pi = s_phi[i];
        acc += pi * (h.x * s_phi[j] + h.y * s_phi[j + 1] +
                     h.z * s_phi[j + 2] + h.w * s_phi[j + 3]);
    }
    acc = warp_sum(acc);
    int warp = tid >> 5, lane = tid & 31;
    if (lane == 0) s_red[warp] = acc;
    __syncthreads();
    if (tid == 0) {
        float t = 0.0f;
#pragma unroll
        for (int w = 0; w < 8; w++) t += s_red[w];
        g_part[m * SPLIT + c] = t;
    }
}

// ---------------------------------------------------------------------------
// Kernel D2: z_new[m] = (1 - g*tau)*z[m] + g*tau*( F[m]*tanh(z[m])
//                        + sum_c g_part[m,c] + (W_in_2 @ I)[m] )
// Warp-per-row: 64 blocks x 256 threads.
// ---------------------------------------------------------------------------
__global__ void kD2(const float* __restrict__ z, const float* __restrict__ F,
                    const float* __restrict__ Win2, const float* __restrict__ I,
                    float* __restrict__ out_z) {
    __shared__ float s_I[KK];
    int tid = threadIdx.x;  // 256
    s_I[tid]       = I[tid];
    s_I[tid + 256] = I[tid + 256];
    __syncthreads();

    int warp = tid >> 5, lane = tid & 31;
    int m = blockIdx.x * 8 + warp;

    const float* w2 = Win2 + (size_t)m * KK;
    float acc = 0.0f;
#pragma unroll
    for (int k = lane; k < KK; k += 32) acc += w2[k] * s_I[k];
    if (lane < SPLIT) acc += g_part[m * SPLIT + lane];
    acc = warp_sum(acc);

    if (lane == 0) {
        float zm  = z[m];
        float psi = tanhf(zm);
        out_z[m] = (1.0f - GAMMA * TAU) * zm +
                   (GAMMA * TAU) * (F[m] * psi + acc);
    }
}

// ---------------------------------------------------------------------------
// Launch: inputs in metadata order: I, x, W, z, C, D, F, H, W_in_1, W_in_2.
// Output: concat(x_new[256], W_new[65536], z_new[512]) = 66304 floats.
// ---------------------------------------------------------------------------
extern "C" void kernel_launch(void* const* d_in, const int* in_sizes, int n_in,
                              void* d_out, int out_size) {
    const float* I    = (const float*)d_in[0];
    const float* x    = (const float*)d_in[1];
    const float* W    = (const float*)d_in[2];
    const float* z    = (const float*)d_in[3];
    const float* C    = (const float*)d_in[4];
    const float* D    = (const float*)d_in[5];
    const float* F    = (const float*)d_in[6];
    const float* H    = (const float*)d_in[7];
    const float* Win1 = (const float*)d_in[8];
    const float* Win2 = (const float*)d_in[9];

    float* out_x = (float*)d_out;            // [0, 256)
    float* out_W = out_x + NN;               // [256, 256+65536)
    float* out_z = out_W + NN2;              // [65792, 66304)

    // Stage 1: x_new + phi(x_new)
    kA<<<NN / 8, 256>>>(x, W, Win1, I, out_x);

    // Stage 2: W_new (depends on phi) — D-bound, 134 MB
    kC<<<NN2 / 8, 256>>>(W, C, D, z, out_W);

    // Stage 3: H @ Phi partials — H-bound, 134 MB
    dim3 gD1(SPLIT, MM);
    kD1<<<gD1, 256>>>(H);

    // Stage 4: z_new combine
    kD2<<<MM / 8, 256>>>(z, F, Win2, I, out_z);
}

// round 2
// speedup vs baseline: 1.0282x; 1.0282x over previous
#include <cuda_runtime.h>

// Problem constants
#define GAMMA 0.1f
#define TAU   0.01f
#define NN    256          // neuron count
#define MM    512          // astrocyte count
#define KK    512          // input dim
#define NN2   (NN * NN)    // 65536
#define SPLIT 16           // chunks per H row
#define CHUNK (NN2 / SPLIT) // 4096 floats per chunk

// Scratch (no allocations allowed in kernel_launch)
__device__ float g_phi[NN];           // sigmoid(x_new)
__device__ float g_part[MM * SPLIT];  // H@Phi partial sums
__device__ float g_win2[MM];          // W_in_2 @ I

__device__ __forceinline__ float warp_sum(float v) {
#pragma unroll
    for (int o = 16; o > 0; o >>= 1) v += __shfl_xor_sync(0xffffffffu, v, o);
    return v;
}

__device__ __forceinline__ float sigmoidf(float v) {
    return 1.0f / (1.0f + expf(-v));
}

// ---------------------------------------------------------------------------
// Kernel A (fused): 96 blocks x 256 threads.
//   blocks 0..31 : x_new = (1-g)x + g*(W @ sigmoid(x)) + W_in_1@I; g_phi
//   blocks 32..95: g_win2 = W_in_2 @ I   (independent of phi, overlaps free)
// ---------------------------------------------------------------------------
__global__ void kA(const float* __restrict__ x, const float* __restrict__ W,
                   const float* __restrict__ Win1, const float* __restrict__ I,
                   const float* __restrict__ Win2, float* __restrict__ out_x) {
    __shared__ float s_I[KK];
    __shared__ float s_phi[NN];
    int tid = threadIdx.x;  // 256
    s_I[tid]       = I[tid];
    s_I[tid + 256] = I[tid + 256];

    int warp = tid >> 5, lane = tid & 31;

    if (blockIdx.x < 32) {
        s_phi[tid] = sigmoidf(x[tid]);
        __syncthreads();
        int row = blockIdx.x * 8 + warp;

        float a1 = 0.0f, a2 = 0.0f;
        const float* wr = W + (size_t)row * NN;
#pragma unroll
        for (int j = lane; j < NN; j += 32) a1 += wr[j] * s_phi[j];
        const float4* w1 = (const float4*)(Win1 + (size_t)row * KK);
        const float4* sI = (const float4*)s_I;
#pragma unroll
        for (int q = 0; q < 4; q++) {
            float4 a = w1[lane + 32 * q];
            float4 b = sI[lane + 32 * q];
            a2 += a.x * b.x + a.y * b.y + a.z * b.z + a.w * b.w;
        }
        a1 = warp_sum(a1);
        a2 = warp_sum(a2);
        if (lane == 0) {
            float xn = (1.0f - GAMMA) * x[row] + GAMMA * a1 + a2;
            out_x[row] = xn;
            g_phi[row] = sigmoidf(xn);
        }
    } else {
        __syncthreads();
        int row = (blockIdx.x - 32) * 8 + warp;  // 0..511
        const float4* w2 = (const float4*)(Win2 + (size_t)row * KK);
        const float4* sI = (const float4*)s_I;
        float acc = 0.0f;
#pragma unroll
        for (int q = 0; q < 4; q++) {
            float4 a = w2[lane + 32 * q];
            float4 b = sI[lane + 32 * q];
            acc += a.x * b.x + a.y * b.y + a.z * b.z + a.w * b.w;
        }
        acc = warp_sum(acc);
        if (lane == 0) g_win2[row] = acc;
    }
}

// ---------------------------------------------------------------------------
// Kernel B (fused kC + kD1): 16384 blocks x 256 threads.
//   blocks [0, 8192)     : W_new rows (warp-per-row, D GEMV + Hebbian term)
//   blocks [8192, 16384) : H@Phi partial sums (block-per-16KB-chunk)
// Both stream 16 KB of a big matrix per block — pure HBM.
// ---------------------------------------------------------------------------
__global__ void kB(const float* __restrict__ W, const float* __restrict__ C,
                   const float* __restrict__ D, const float* __restrict__ z,
                   const float* __restrict__ H, float* __restrict__ out_W) {
    __shared__ float s_vec[MM];   // psi(z) for kC branch, phi (256 used) for kD1
    __shared__ float s_red[8];
    int tid = threadIdx.x;  // 256
    int warp = tid >> 5, lane = tid & 31;

    if (blockIdx.x < 8192) {
        // ---- W_new branch ----
        s_vec[tid]       = tanhf(z[tid]);
        s_vec[tid + 256] = tanhf(z[tid + 256]);
        __syncthreads();

        int p = blockIdx.x * 8 + warp;
        const float4* dr = (const float4*)(D + (size_t)p * MM);
        const float4* ps = (const float4*)s_vec;
        float acc = 0.0f;
#pragma unroll
        for (int q = 0; q < 4; q++) {
            int idx = lane + 32 * q;       // 128 float4 per 512-float row
            float4 d = dr[idx];
            float4 s = ps[idx];
            acc += d.x * s.x + d.y * s.y + d.z * s.z + d.w * s.w;
        }
        acc = warp_sum(acc);
        if (lane == 0) {
            int i = p >> 8, j = p & 255;
            float ph = g_phi[i] * g_phi[j];
            out_W[p] = (1.0f - GAMMA) * W[p] + GAMMA * (C[p] * ph + acc);
        }
    } else {
        // ---- H@Phi partials branch ----
        s_vec[tid] = g_phi[tid];
        __syncthreads();

        int b = blockIdx.x - 8192;
        int c = b & (SPLIT - 1);  // chunk
        int m = b >> 4;           // row
        const float4* hr = (const float4*)(H + (size_t)m * NN2 + (size_t)c * CHUNK);

        float acc = 0.0f;
#pragma unroll
        for (int q = 0; q < 4; q++) {
            int f = tid + 256 * q;        // float4 index within chunk (0..1023)
            int p = c * CHUNK + f * 4;    // element index within row
            float4 h = hr[f];
            int i = p >> 8;
            int j = p & 255;              // multiple of 4, j+3 <= 255
            float pi = s_vec[i];
            acc += pi * (h.x * s_vec[j] + h.y * s_vec[j + 1] +
                         h.z * s_vec[j + 2] + h.w * s_vec[j + 3]);
        }
        acc = warp_sum(acc);
        if (lane == 0) s_red[warp] = acc;
        __syncthreads();
        if (tid == 0) {
            float t = 0.0f;
#pragma unroll
            for (int w = 0; w < 8; w++) t += s_red[w];
            g_part[m * SPLIT + c] = t;
        }
    }
}

// ---------------------------------------------------------------------------
// Kernel C (combine): z_new[m] = (1-g*tau)*z[m] + g*tau*( F[m]*tanh(z[m])
//                       + sum_c g_part[m,c] + g_win2[m] )
// 2 blocks x 256 threads, thread-per-row, float4 partial loads. ~40 KB total.
// ---------------------------------------------------------------------------
__global__ void kZ(const float* __restrict__ z, const float* __restrict__ F,
                   float* __restrict__ out_z) {
    int m = blockIdx.x * 256 + threadIdx.x;  // 0..511
    const float4* pp = (const float4*)(g_part + m * SPLIT);
    float4 p0 = pp[0], p1 = pp[1], p2 = pp[2], p3 = pp[3];
    float acc = (p0.x + p0.y + p0.z + p0.w) + (p1.x + p1.y + p1.z + p1.w) +
                (p2.x + p2.y + p2.z + p2.w) + (p3.x + p3.y + p3.z + p3.w);
    acc += g_win2[m];
    float zm  = z[m];
    float psi = tanhf(zm);
    out_z[m] = (1.0f - GAMMA * TAU) * zm +
               (GAMMA * TAU) * (F[m] * psi + acc);
}

// ---------------------------------------------------------------------------
// Launch: inputs in metadata order: I, x, W, z, C, D, F, H, W_in_1, W_in_2.
// Output: concat(x_new[256], W_new[65536], z_new[512]) = 66304 floats.
// ---------------------------------------------------------------------------
extern "C" void kernel_launch(void* const* d_in, const int* in_sizes, int n_in,
                              void* d_out, int out_size) {
    const float* I    = (const float*)d_in[0];
    const float* x    = (const float*)d_in[1];
    const float* W    = (const float*)d_in[2];
    const float* z    = (const float*)d_in[3];
    const float* C    = (const float*)d_in[4];
    const float* D    = (const float*)d_in[5];
    const float* F    = (const float*)d_in[6];
    const float* H    = (const float*)d_in[7];
    const float* Win1 = (const float*)d_in[8];
    const float* Win2 = (const float*)d_in[9];

    float* out_x = (float*)d_out;            // [0, 256)
    float* out_W = out_x + NN;               // [256, 256+65536)
    float* out_z = out_W + NN2;              // [65792, 66304)

    // Stage 1: x_new + phi(x_new) + W_in_2@I (independent, same grid)
    kA<<<96, 256>>>(x, W, Win1, I, Win2, out_x);

    // Stage 2: fused W_new + H@Phi partials — streams D and H (268 MB)
    kB<<<16384, 256>>>(W, C, D, z, H, out_W);

    // Stage 3: z_new combine (tiny)
    kZ<<<2, 256>>>(z, F, out_z);
}